// round 17
// baseline (speedup 1.0000x reference)
#include <cuda_runtime.h>
#include <cuda_bf16.h>
#include <cstdint>

// ---------------------------------------------------------------------------
// Problem constants
// ---------------------------------------------------------------------------
#define BATCH   4
#define SEQ     2048
#define DMODEL  512
#define DHID    2048
#define NHEADS  2
#define GSZ     256
#define MTOT    (BATCH * SEQ)       // 8192

// softmax scale folded into Wq: 1/sqrt(256) * log2(e)
#define QSC 0.09016994374947424f

// ---------------------------------------------------------------------------
// Scratch (device globals) — two sets so blocks 0 and 1 batch together
// ---------------------------------------------------------------------------
__device__ __nv_bfloat16 g_qb[MTOT * DMODEL],  g_qb2[MTOT * DMODEL];
__device__ __nv_bfloat16 g_kb[MTOT * DMODEL],  g_kb2[MTOT * DMODEL];
__device__ __nv_bfloat16 g_vb[MTOT * DMODEL],  g_vb2[MTOT * DMODEL];
__device__ __nv_bfloat16 g_kb3[MTOT * DMODEL];           // block2 K (early)
__device__ float g_att[MTOT * DMODEL], g_att2[MTOT * DMODEL];
__device__ float g_x  [MTOT * DMODEL], g_x2  [MTOT * DMODEL];
__device__ float g_y  [MTOT * DMODEL], g_y2  [MTOT * DMODEL];
__device__ float g_css[MTOT * DMODEL];
__device__ float g_cqq[MTOT * DMODEL];

__device__ __nv_bfloat16 g_wqh[3*DMODEL*DMODEL], g_wql[3*DMODEL*DMODEL];
__device__ __nv_bfloat16 g_wkh[3*DMODEL*DMODEL], g_wkl[3*DMODEL*DMODEL];
__device__ __nv_bfloat16 g_wvh[3*DMODEL*DMODEL], g_wvl[3*DMODEL*DMODEL];
__device__ __nv_bfloat16 g_w1h[3*DHID*DMODEL],   g_w1l[3*DHID*DMODEL];
__device__ __nv_bfloat16 g_w2h[3*DMODEL*DHID],   g_w2l[3*DMODEL*DHID];
__device__ __nv_bfloat16 g_fmh[MTOT*DMODEL], g_fml[MTOT*DMODEL];
__device__ __nv_bfloat16 g_fsh[MTOT*DMODEL], g_fsl[MTOT*DMODEL];
__device__ __nv_bfloat16 g_fqh[MTOT*DMODEL], g_fql[MTOT*DMODEL];
__device__ __nv_bfloat16 g_cssh[MTOT*DMODEL], g_cssl[MTOT*DMODEL];
__device__ __nv_bfloat16 g_cqqh[MTOT*DMODEL], g_cqql[MTOT*DMODEL];
__device__ __nv_bfloat16 g_xh[MTOT*DMODEL],  g_xl[MTOT*DMODEL];
__device__ __nv_bfloat16 g_xh2[MTOT*DMODEL], g_xl2[MTOT*DMODEL];
__device__ __nv_bfloat16 g_hh[MTOT*DHID],    g_hl[MTOT*DHID];
__device__ __nv_bfloat16 g_hh2[MTOT*DHID],   g_hl2[MTOT*DHID];

// ---------------------------------------------------------------------------
// helpers
// ---------------------------------------------------------------------------
__device__ __forceinline__ uint32_t sptr(const void* p) {
    return (uint32_t)__cvta_generic_to_shared(p);
}
__device__ __forceinline__ void ldm4(uint32_t a, uint32_t& r0, uint32_t& r1,
                                     uint32_t& r2, uint32_t& r3) {
    asm volatile("ldmatrix.sync.aligned.m8n8.x4.shared.b16 {%0,%1,%2,%3},[%4];"
                 : "=r"(r0), "=r"(r1), "=r"(r2), "=r"(r3) : "r"(a));
}
__device__ __forceinline__ void ldm4t(uint32_t a, uint32_t& r0, uint32_t& r1,
                                      uint32_t& r2, uint32_t& r3) {
    asm volatile("ldmatrix.sync.aligned.m8n8.x4.trans.shared.b16 {%0,%1,%2,%3},[%4];"
                 : "=r"(r0), "=r"(r1), "=r"(r2), "=r"(r3) : "r"(a));
}
__device__ __forceinline__ void mma_bf16(float c[4], const uint32_t a[4],
                                         const uint32_t b[2]) {
    asm volatile(
        "mma.sync.aligned.m16n8k16.row.col.f32.bf16.bf16.f32 "
        "{%0,%1,%2,%3},{%4,%5,%6,%7},{%8,%9},{%0,%1,%2,%3};"
        : "+f"(c[0]), "+f"(c[1]), "+f"(c[2]), "+f"(c[3])
        : "r"(a[0]), "r"(a[1]), "r"(a[2]), "r"(a[3]), "r"(b[0]), "r"(b[1]));
}
__device__ __forceinline__ float e2(float x) {
    float y; asm("ex2.approx.ftz.f32 %0,%1;" : "=f"(y) : "f"(x)); return y;
}
__device__ __forceinline__ uint32_t packbf(float a, float b) {
    const __nv_bfloat162 t = __float22bfloat162_rn(make_float2(a, b));
    return *reinterpret_cast<const uint32_t*>(&t);
}
__device__ __forceinline__ void split2(float v, __nv_bfloat16& h, __nv_bfloat16& l) {
    h = __float2bfloat16(v);
    l = __float2bfloat16(v - __bfloat162float(h));
}
__device__ __forceinline__ void cpa16(uint32_t s, const void* g) {
    asm volatile("cp.async.cg.shared.global [%0],[%1],16;" :: "r"(s), "l"(g));
}
__device__ __forceinline__ void cpa_commit() {
    asm volatile("cp.async.commit_group;");
}
template <int N>
__device__ __forceinline__ void cpa_wait() {
    asm volatile("cp.async.wait_group %0;" :: "n"(N));
}

// ---------------------------------------------------------------------------
// fused input split: {Fm, Fs, Fq} fp32 -> bf16 (hi, lo)
// ---------------------------------------------------------------------------
#define SEG4 (MTOT * DMODEL / 4)

__global__ __launch_bounds__(256)
void split_in_kernel(const float* __restrict__ Fm, const float* __restrict__ Fs,
                     const float* __restrict__ Fq)
{
    const int i = blockIdx.x * 256 + threadIdx.x;
    if (i >= 3 * SEG4) return;
    const int seg = i / SEG4;
    const int off = i - seg * SEG4;
    const float* src = (seg == 0) ? Fm : (seg == 1) ? Fs : Fq;
    __nv_bfloat16* dh = (seg == 0) ? g_fmh : (seg == 1) ? g_fsh : g_fqh;
    __nv_bfloat16* dl = (seg == 0) ? g_fml : (seg == 1) ? g_fsl : g_fql;
    const float4 v = *(const float4*)(src + (size_t)off * 4);
    __nv_bfloat16 h0, h1, h2, h3, l0, l1, l2, l3;
    split2(v.x, h0, l0); split2(v.y, h1, l1);
    split2(v.z, h2, l2); split2(v.w, h3, l3);
    *(__nv_bfloat162*)(dh + (size_t)off * 4)     = __nv_bfloat162(h0, h1);
    *(__nv_bfloat162*)(dh + (size_t)off * 4 + 2) = __nv_bfloat162(h2, h3);
    *(__nv_bfloat162*)(dl + (size_t)off * 4)     = __nv_bfloat162(l0, l1);
    *(__nv_bfloat162*)(dl + (size_t)off * 4 + 2) = __nv_bfloat162(l2, l3);
}

// ---------------------------------------------------------------------------
// fused weight split: {Wq(scaled by QSC), Wk, Wv, w1, w2} fp32 -> bf16 (hi,lo)
// ---------------------------------------------------------------------------
#define WQ4 (3 * DMODEL * DMODEL / 4)
#define W14 (3 * DHID * DMODEL / 4)
#define WTOT4 (3 * WQ4 + 2 * W14)

__global__ __launch_bounds__(256)
void split_w_kernel(const float* __restrict__ Wq, const float* __restrict__ Wk,
                    const float* __restrict__ Wv, const float* __restrict__ w1,
                    const float* __restrict__ w2)
{
    const int i = blockIdx.x * 256 + threadIdx.x;
    if (i >= WTOT4) return;
    const float* src; __nv_bfloat16 *dh, *dl; int off; float sc = 1.f;
    if (i < WQ4)                 { src = Wq; dh = g_wqh; dl = g_wql; off = i; sc = QSC; }
    else if (i < 2 * WQ4)        { src = Wk; dh = g_wkh; dl = g_wkl; off = i - WQ4; }
    else if (i < 3 * WQ4)        { src = Wv; dh = g_wvh; dl = g_wvl; off = i - 2 * WQ4; }
    else if (i < 3 * WQ4 + W14)  { src = w1; dh = g_w1h; dl = g_w1l; off = i - 3 * WQ4; }
    else                         { src = w2; dh = g_w2h; dl = g_w2l; off = i - 3 * WQ4 - W14; }
    float4 v = *(const float4*)(src + (size_t)off * 4);
    v.x *= sc; v.y *= sc; v.z *= sc; v.w *= sc;
    __nv_bfloat16 h0, h1, h2, h3, l0, l1, l2, l3;
    split2(v.x, h0, l0); split2(v.y, h1, l1);
    split2(v.z, h2, l2); split2(v.w, h3, l3);
    *(__nv_bfloat162*)(dh + (size_t)off * 4)     = __nv_bfloat162(h0, h1);
    *(__nv_bfloat162*)(dh + (size_t)off * 4 + 2) = __nv_bfloat162(h2, h3);
    *(__nv_bfloat162*)(dl + (size_t)off * 4)     = __nv_bfloat162(l0, l1);
    *(__nv_bfloat162*)(dl + (size_t)off * 4 + 2) = __nv_bfloat162(l2, l3);
}

// ---------------------------------------------------------------------------
// bf16 3-pass split GEMM body (validated R10 inner loop)
// OUT: 0 -> fp32 C;  1 -> relu + bf16 split (Ch, Cl);  2 -> bf16 (Ch only)
// ---------------------------------------------------------------------------
#define TBM 128
#define TBN 128
#define TBK 32
#define TAS 40
#define REGB  (TBM * TAS * 2)
#define BUFSZ (4 * REGB)
#define GEMM_SMEM (2 * BUFSZ)

extern __shared__ char gsm[];

template <int OUT>
__device__ __forceinline__
void gemm_body(const __nv_bfloat16* __restrict__ Agh, const __nv_bfloat16* __restrict__ Agl,
               const __nv_bfloat16* __restrict__ Bgh, const __nv_bfloat16* __restrict__ Bgl,
               float* __restrict__ C, __nv_bfloat16* __restrict__ Ch,
               __nv_bfloat16* __restrict__ Cl, int M, int N, int K)
{
    const int tid  = threadIdx.x;
    const int lane = tid & 31;
    const int wid  = tid >> 5;
    const int wm   = wid & 1;
    const int wn   = wid >> 1;
    const int bm   = blockIdx.y * TBM;
    const int bn   = blockIdx.x * TBN;

    const uint32_t sbase = sptr(gsm);

    auto load_tile = [&](int buf, int k0) {
        const uint32_t b = sbase + buf * BUFSZ;
#pragma unroll
        for (int j = 0; j < 4; ++j) {
            const int c = tid + j * 128;
            const int row = c >> 2, kc = (c & 3) << 3;
            const uint32_t so = (uint32_t)(row * TAS + kc) * 2;
            const size_t goA = (size_t)(bm + row) * K + k0 + kc;
            const size_t goB = (size_t)(bn + row) * K + k0 + kc;
            cpa16(b + so,            Agh + goA);
            cpa16(b + REGB + so,     Agl + goA);
            cpa16(b + 2 * REGB + so, Bgh + goB);
            cpa16(b + 3 * REGB + so, Bgl + goB);
        }
        cpa_commit();
    };

    float c[4][8][4];
#pragma unroll
    for (int mi = 0; mi < 4; ++mi)
#pragma unroll
        for (int ni = 0; ni < 8; ++ni)
#pragma unroll
            for (int e = 0; e < 4; ++e) c[mi][ni][e] = 0.f;

    const int lmA = lane & 15;
    const int lkA = (lane >> 4) << 3;
    const int lnB = ((lane >> 4) & 1) * 8 + (lane & 7);
    const int lkB = ((lane >> 3) & 1) * 8;
    const uint32_t relA = (uint32_t)((wm * 64 + lmA) * TAS + lkA) * 2;
    const uint32_t relB = (uint32_t)((wn * 64 + lnB) * TAS + lkB) * 2;

    const int niter = K / TBK;
    load_tile(0, 0);

    for (int it = 0; it < niter; ++it) {
        const int cur = it & 1;
        if (it + 1 < niter) { load_tile(cur ^ 1, (it + 1) * TBK); cpa_wait<1>(); }
        else cpa_wait<0>();
        __syncthreads();

        const uint32_t b = sbase + cur * BUFSZ;
        const uint32_t aAh = b + relA,            aAl = b + REGB + relA;
        const uint32_t aBh = b + 2 * REGB + relB, aBl = b + 3 * REGB + relB;

#pragma unroll
        for (int ks = 0; ks < 2; ++ks) {
            const uint32_t ko = ks * 32;
            uint32_t bhf[8][2], blf[8][2];
#pragma unroll
            for (int p = 0; p < 4; ++p) {
                ldm4(aBh + p * (16 * TAS * 2) + ko,
                     bhf[2*p][0], bhf[2*p][1], bhf[2*p+1][0], bhf[2*p+1][1]);
                ldm4(aBl + p * (16 * TAS * 2) + ko,
                     blf[2*p][0], blf[2*p][1], blf[2*p+1][0], blf[2*p+1][1]);
            }
#pragma unroll
            for (int mi = 0; mi < 4; ++mi) {
                uint32_t ah[4], al[4];
                ldm4(aAh + mi * (16 * TAS * 2) + ko, ah[0], ah[1], ah[2], ah[3]);
                ldm4(aAl + mi * (16 * TAS * 2) + ko, al[0], al[1], al[2], al[3]);
#pragma unroll
                for (int ni = 0; ni < 8; ++ni) mma_bf16(c[mi][ni], ah, bhf[ni]);
#pragma unroll
                for (int ni = 0; ni < 8; ++ni) mma_bf16(c[mi][ni], ah, blf[ni]);
#pragma unroll
                for (int ni = 0; ni < 8; ++ni) mma_bf16(c[mi][ni], al, bhf[ni]);
            }
        }
        __syncthreads();
    }

#pragma unroll
    for (int mi = 0; mi < 4; ++mi) {
        const int row0 = bm + wm * 64 + mi * 16 + (lane >> 2);
#pragma unroll
        for (int ni = 0; ni < 8; ++ni) {
            const int col = bn + wn * 64 + ni * 8 + ((lane & 3) << 1);
            float v0 = c[mi][ni][0], v1 = c[mi][ni][1];
            float v2 = c[mi][ni][2], v3 = c[mi][ni][3];
            if (OUT == 0) {
                float2 a; a.x = v0; a.y = v1;
                float2 bq; bq.x = v2; bq.y = v3;
                *(float2*)&C[(size_t)row0 * N + col]       = a;
                *(float2*)&C[(size_t)(row0 + 8) * N + col] = bq;
            } else if (OUT == 1) {
                v0 = fmaxf(v0, 0.f); v1 = fmaxf(v1, 0.f);
                v2 = fmaxf(v2, 0.f); v3 = fmaxf(v3, 0.f);
                __nv_bfloat16 h0, h1, h2, h3, l0, l1, l2, l3;
                split2(v0, h0, l0); split2(v1, h1, l1);
                split2(v2, h2, l2); split2(v3, h3, l3);
                *(__nv_bfloat162*)&Ch[(size_t)row0 * N + col]       = __nv_bfloat162(h0, h1);
                *(__nv_bfloat162*)&Cl[(size_t)row0 * N + col]       = __nv_bfloat162(l0, l1);
                *(__nv_bfloat162*)&Ch[(size_t)(row0 + 8) * N + col] = __nv_bfloat162(h2, h3);
                *(__nv_bfloat162*)&Cl[(size_t)(row0 + 8) * N + col] = __nv_bfloat162(l2, l3);
            } else {
                *(__nv_bfloat162*)&Ch[(size_t)row0 * N + col] =
                    __nv_bfloat162(__float2bfloat16(v0), __float2bfloat16(v1));
                *(__nv_bfloat162*)&Ch[(size_t)(row0 + 8) * N + col] =
                    __nv_bfloat162(__float2bfloat16(v2), __float2bfloat16(v3));
            }
        }
    }
}

// batched GEMM: blockIdx.z selects operand set from a by-value arg struct
#define GZMAX 8
struct GArgs {
    const __nv_bfloat16* ah[GZMAX];
    const __nv_bfloat16* al[GZMAX];
    const __nv_bfloat16* bh[GZMAX];
    const __nv_bfloat16* bl[GZMAX];
    float*               c [GZMAX];
    __nv_bfloat16*       ch[GZMAX];
    __nv_bfloat16*       cl[GZMAX];
};

template <int OUT>
__global__ __launch_bounds__(128, 2)
void gemm_z(GArgs a, int N, int K)
{
    const int z = blockIdx.z;
    gemm_body<OUT>(a.ah[z], a.al[z], a.bh[z], a.bl[z],
                   a.c[z], a.ch[z], a.cl[z], MTOT, N, K);
}

// ---------------------------------------------------------------------------
// Tensor-core flash attention — bf16 in, V row-major + ldmatrix.trans for PV
// blockIdx.z in [0, 4*nsets): set = z>>2, batch = z&3
// ---------------------------------------------------------------------------
#define FM  64
#define FN  64
#define FQS 264
#define FA_SMEM_BYTES (3 * FM * FQS * 2)    // 101376

extern __shared__ char fa_raw[];

__global__ __launch_bounds__(128, 2)
void flash_tc(const __nv_bfloat16* __restrict__ Q1, const __nv_bfloat16* __restrict__ K1,
              const __nv_bfloat16* __restrict__ V1, float* __restrict__ O1,
              const __nv_bfloat16* __restrict__ Q2, const __nv_bfloat16* __restrict__ K2,
              const __nv_bfloat16* __restrict__ V2, float* __restrict__ O2)
{
    __nv_bfloat16* Qs = (__nv_bfloat16*)fa_raw;
    __nv_bfloat16* Ks = Qs + FM * FQS;
    __nv_bfloat16* Vs = Ks + FN * FQS;

    const int tid  = threadIdx.x;
    const int lane = tid & 31;
    const int w    = tid >> 5;
    const int qbase = blockIdx.x * FM;
    const int h = blockIdx.y;
    const int b = blockIdx.z & 3;
    const int set = blockIdx.z >> 2;
    const __nv_bfloat16* Q = set ? Q2 : Q1;
    const __nv_bfloat16* K = set ? K2 : K1;
    const __nv_bfloat16* V = set ? V2 : V1;
    float* O = set ? O2 : O1;
    const size_t bstride = (size_t)SEQ * DMODEL;
    const __nv_bfloat16* Qb = Q + b * bstride + h * GSZ;
    const __nv_bfloat16* Kb = K + b * bstride + h * GSZ;
    const __nv_bfloat16* Vb = V + b * bstride + h * GSZ;

    const int lmA = lane & 15;
    const int lkA = (lane >> 4) << 3;
    const int lnB = ((lane >> 4) & 1) * 8 + (lane & 7);
    const int lkB = ((lane >> 3) & 1) * 8;

    const uint32_t aQ = sptr(Qs) + (uint32_t)((w * 16 + lmA) * FQS + lkA) * 2;
    const uint32_t aK = sptr(Ks) + (uint32_t)(lnB * FQS + lkB) * 2;
    const uint32_t aV = sptr(Vs) + (uint32_t)((lane & 15) * FQS + (lane >> 4) * 8) * 2;

#pragma unroll
    for (int j = 0; j < 16; ++j) {
        const int idx = tid + j * 128;
        const int row = idx >> 5, c8 = idx & 31;
        const uint4 u = *(const uint4*)(Qb + (size_t)(qbase + row) * DMODEL + c8 * 8);
        *(uint4*)(Qs + row * FQS + c8 * 8) = u;
    }

    float mA = -1e30f, mB = -1e30f, lA = 0.f, lB = 0.f;
    float o[32][4];
#pragma unroll
    for (int f = 0; f < 32; ++f)
#pragma unroll
        for (int e = 0; e < 4; ++e) o[f][e] = 0.f;

    for (int kb = 0; kb < SEQ; kb += FN) {
        __syncthreads();
#pragma unroll
        for (int j = 0; j < 16; ++j) {
            const int idx = tid + j * 128;
            const int row = idx >> 5, c8 = idx & 31;
            const uint4 uk = *(const uint4*)(Kb + (size_t)(kb + row) * DMODEL + c8 * 8);
            *(uint4*)(Ks + row * FQS + c8 * 8) = uk;
            const uint4 uv = *(const uint4*)(Vb + (size_t)(kb + row) * DMODEL + c8 * 8);
            *(uint4*)(Vs + row * FQS + c8 * 8) = uv;
        }
        __syncthreads();

        float s[8][4];
#pragma unroll
        for (int f = 0; f < 8; ++f)
#pragma unroll
            for (int e = 0; e < 4; ++e) s[f][e] = 0.f;

#pragma unroll
        for (int ks = 0; ks < 16; ++ks) {
            uint32_t af[4];
            ldm4(aQ + ks * 32, af[0], af[1], af[2], af[3]);
#pragma unroll
            for (int g = 0; g < 4; ++g) {
                uint32_t b0[2], b1[2];
                ldm4(aK + (uint32_t)(g * 16 * FQS) * 2 + ks * 32,
                     b0[0], b0[1], b1[0], b1[1]);
                mma_bf16(s[2 * g],     af, b0);
                mma_bf16(s[2 * g + 1], af, b1);
            }
        }

        float mxA = -1e30f, mxB = -1e30f;
#pragma unroll
        for (int f = 0; f < 8; ++f) {
            mxA = fmaxf(mxA, fmaxf(s[f][0], s[f][1]));
            mxB = fmaxf(mxB, fmaxf(s[f][2], s[f][3]));
        }
        mxA = fmaxf(mxA, __shfl_xor_sync(0xffffffffu, mxA, 1));
        mxA = fmaxf(mxA, __shfl_xor_sync(0xffffffffu, mxA, 2));
        mxB = fmaxf(mxB, __shfl_xor_sync(0xffffffffu, mxB, 1));
        mxB = fmaxf(mxB, __shfl_xor_sync(0xffffffffu, mxB, 2));
        const float mnA = fmaxf(mA, mxA);
        const float mnB = fmaxf(mB, mxB);
        float sumA = 0.f, sumB = 0.f;
#pragma unroll
        for (int f = 0; f < 8; ++f) {
            s[f][0] = e2(s[f][0] - mnA); s[f][1] = e2(s[f][1] - mnA);
            s[f][2] = e2(s[f][2] - mnB); s[f][3] = e2(s[f][3] - mnB);
            sumA += s[f][0] + s[f][1];
            sumB += s[f][2] + s[f][3];
        }
        sumA += __shfl_xor_sync(0xffffffffu, sumA, 1);
        sumA += __shfl_xor_sync(0xffffffffu, sumA, 2);
        sumB += __shfl_xor_sync(0xffffffffu, sumB, 1);
        sumB += __shfl_xor_sync(0xffffffffu, sumB, 2);
        const float ccA = e2(mA - mnA);
        const float ccB = e2(mB - mnB);
        lA = lA * ccA + sumA; mA = mnA;
        lB = lB * ccB + sumB; mB = mnB;

#pragma unroll
        for (int f = 0; f < 32; ++f) {
            o[f][0] *= ccA; o[f][1] *= ccA;
            o[f][2] *= ccB; o[f][3] *= ccB;
        }

#pragma unroll
        for (int kf = 0; kf < 4; ++kf) {
            uint32_t ap[4];
            ap[0] = packbf(s[2 * kf][0],     s[2 * kf][1]);
            ap[1] = packbf(s[2 * kf][2],     s[2 * kf][3]);
            ap[2] = packbf(s[2 * kf + 1][0], s[2 * kf + 1][1]);
            ap[3] = packbf(s[2 * kf + 1][2], s[2 * kf + 1][3]);
            const uint32_t aVk = aV + (uint32_t)(kf * 16 * FQS) * 2;
#pragma unroll
            for (int g = 0; g < 16; ++g) {
                uint32_t b0[2], b1[2];
                ldm4t(aVk + g * 32, b0[0], b0[1], b1[0], b1[1]);
                mma_bf16(o[2 * g],     ap, b0);
                mma_bf16(o[2 * g + 1], ap, b1);
            }
        }
    }

    const float liA = 1.f / lA;
    const float liB = 1.f / lB;
    const int rowA = qbase + w * 16 + (lane >> 2);
    float* Ob = O + b * bstride + h * GSZ;
#pragma unroll
    for (int f = 0; f < 32; ++f) {
        const int col = f * 8 + ((lane & 3) << 1);
        float2 rA; rA.x = o[f][0] * liA; rA.y = o[f][1] * liA;
        float2 rB; rB.x = o[f][2] * liB; rB.y = o[f][3] * liB;
        *(float2*)&Ob[(size_t)rowA * DMODEL + col]       = rA;
        *(float2*)&Ob[(size_t)(rowA + 8) * DMODEL + col] = rB;
    }
}

// ---------------------------------------------------------------------------
// out = LayerNorm(X + R); optionally emit bf16 (hi, lo) split
// ---------------------------------------------------------------------------
__global__ __launch_bounds__(128)
void add_ln_kernel(const float* __restrict__ X, const float* __restrict__ R,
                   const float* __restrict__ g, const float* __restrict__ bt,
                   float eps, float* __restrict__ out,
                   __nv_bfloat16* __restrict__ oh, __nv_bfloat16* __restrict__ ol,
                   int doSplit)
{
    const int row = blockIdx.x;
    const int tid = threadIdx.x;
    float4 v = *(const float4*)(X + (size_t)row * DMODEL + tid * 4);
    const float4 rr = *(const float4*)(R + (size_t)row * DMODEL + tid * 4);
    v.x += rr.x; v.y += rr.y; v.z += rr.z; v.w += rr.w;
    float s  = v.x + v.y + v.z + v.w;
    float sq = v.x * v.x + v.y * v.y + v.z * v.z + v.w * v.w;
#pragma unroll
    for (int off = 16; off; off >>= 1) {
        s  += __shfl_xor_sync(0xffffffffu, s,  off);
        sq += __shfl_xor_sync(0xffffffffu, sq, off);
    }
    __shared__ float ssum[4], ssq[4];
    const int w = tid >> 5, l = tid & 31;
    if (l == 0) { ssum[w] = s; ssq[w] = sq; }
    __syncthreads();
    s  = ssum[0] + ssum[1] + ssum[2] + ssum[3];
    sq = ssq[0]  + ssq[1]  + ssq[2]  + ssq[3];
    const float mean = s * (1.f / DMODEL);
    const float var  = sq * (1.f / DMODEL) - mean * mean;
    const float rstd = rsqrtf(var + eps);
    const float4 gg = *(const float4*)(g  + tid * 4);
    const float4 bb = *(const float4*)(bt + tid * 4);
    float4 r;
    r.x = (v.x - mean) * rstd * gg.x + bb.x;
    r.y = (v.y - mean) * rstd * gg.y + bb.y;
    r.z = (v.z - mean) * rstd * gg.z + bb.z;
    r.w = (v.w - mean) * rstd * gg.w + bb.w;
    *(float4*)(out + (size_t)row * DMODEL + tid * 4) = r;
    if (doSplit) {
        __nv_bfloat16 h0, h1, h2, h3, l0, l1, l2, l3;
        split2(r.x, h0, l0); split2(r.y, h1, l1);
        split2(r.z, h2, l2); split2(r.w, h3, l3);
        const size_t o = (size_t)row * DMODEL + tid * 4;
        *(__nv_bfloat162*)(oh + o)     = __nv_bfloat162(h0, h1);
        *(__nv_bfloat162*)(oh + o + 2) = __nv_bfloat162(h2, h3);
        *(__nv_bfloat162*)(ol + o)     = __nv_bfloat162(l0, l1);
        *(__nv_bfloat162*)(ol + o + 2) = __nv_bfloat162(l2, l3);
    }
}

// ---------------------------------------------------------------------------
// host side — blocks 0 and 1 batched into wide grid.z launches
// ---------------------------------------------------------------------------
extern "C" void kernel_launch(void* const* d_in, const int* in_sizes, int n_in,
                              void* d_out, int out_size)
{
    (void)in_sizes; (void)n_in; (void)out_size;
    const float* Fm   = (const float*)d_in[0];
    const float* Fs   = (const float*)d_in[1];
    const float* Fq   = (const float*)d_in[2];
    const float* Wq   = (const float*)d_in[3];
    const float* Wk   = (const float*)d_in[4];
    const float* Wv   = (const float*)d_in[5];
    const float* lng  = (const float*)d_in[6];
    const float* lnb  = (const float*)d_in[7];
    const float* w1   = (const float*)d_in[8];
    const float* w2   = (const float*)d_in[9];
    const float* flg  = (const float*)d_in[10];
    const float* flb  = (const float*)d_in[11];
    float* out = (float*)d_out;

    float *att, *x, *y, *att2, *x2, *y2, *css, *cqq;
    cudaGetSymbolAddress((void**)&att,  g_att);
    cudaGetSymbolAddress((void**)&x,    g_x);
    cudaGetSymbolAddress((void**)&y,    g_y);
    cudaGetSymbolAddress((void**)&att2, g_att2);
    cudaGetSymbolAddress((void**)&x2,   g_x2);
    cudaGetSymbolAddress((void**)&y2,   g_y2);
    cudaGetSymbolAddress((void**)&css,  g_css);
    cudaGetSymbolAddress((void**)&cqq,  g_cqq);

    __nv_bfloat16 *qb, *kb, *vb, *qb2, *kb2, *vb2, *kb3;
    __nv_bfloat16 *wqh, *wql, *wkh, *wkl, *wvh, *wvl, *w1h, *w1l, *w2h, *w2l;
    __nv_bfloat16 *fmh, *fml, *fsh, *fsl, *fqh, *fql;
    __nv_bfloat16 *cssh, *cssl, *cqqh, *cqql;
    __nv_bfloat16 *xh, *xl, *xh2, *xl2, *hh, *hl, *hh2, *hl2;
    cudaGetSymbolAddress((void**)&qb,  g_qb);
    cudaGetSymbolAddress((void**)&kb,  g_kb);
    cudaGetSymbolAddress((void**)&vb,  g_vb);
    cudaGetSymbolAddress((void**)&qb2, g_qb2);
    cudaGetSymbolAddress((void**)&kb2, g_kb2);
    cudaGetSymbolAddress((void**)&vb2, g_vb2);
    cudaGetSymbolAddress((void**)&kb3, g_kb3);
    cudaGetSymbolAddress((void**)&wqh, g_wqh); cudaGetSymbolAddress((void**)&wql, g_wql);
    cudaGetSymbolAddress((void**)&wkh, g_wkh); cudaGetSymbolAddress((void**)&wkl, g_wkl);
    cudaGetSymbolAddress((void**)&wvh, g_wvh); cudaGetSymbolAddress((void**)&wvl, g_wvl);
    cudaGetSymbolAddress((void**)&w1h, g_w1h); cudaGetSymbolAddress((void**)&w1l, g_w1l);
    cudaGetSymbolAddress((void**)&w2h, g_w2h); cudaGetSymbolAddress((void**)&w2l, g_w2l);
    cudaGetSymbolAddress((void**)&fmh, g_fmh); cudaGetSymbolAddress((void**)&fml, g_fml);
    cudaGetSymbolAddress((void**)&fsh, g_fsh); cudaGetSymbolAddress((void**)&fsl, g_fsl);
    cudaGetSymbolAddress((void**)&fqh, g_fqh); cudaGetSymbolAddress((void**)&fql, g_fql);
    cudaGetSymbolAddress((void**)&cssh, g_cssh); cudaGetSymbolAddress((void**)&cssl, g_cssl);
    cudaGetSymbolAddress((void**)&cqqh, g_cqqh); cudaGetSymbolAddress((void**)&cqql, g_cqql);
    cudaGetSymbolAddress((void**)&xh,  g_xh);  cudaGetSymbolAddress((void**)&xl,  g_xl);
    cudaGetSymbolAddress((void**)&xh2, g_xh2); cudaGetSymbolAddress((void**)&xl2, g_xl2);
    cudaGetSymbolAddress((void**)&hh,  g_hh);  cudaGetSymbolAddress((void**)&hl,  g_hl);
    cudaGetSymbolAddress((void**)&hh2, g_hh2); cudaGetSymbolAddress((void**)&hl2, g_hl2);

    cudaFuncSetAttribute(flash_tc, cudaFuncAttributeMaxDynamicSharedMemorySize,
                         FA_SMEM_BYTES);
    cudaFuncSetAttribute(gemm_z<0>, cudaFuncAttributeMaxDynamicSharedMemorySize,
                         GEMM_SMEM);
    cudaFuncSetAttribute(gemm_z<1>, cudaFuncAttributeMaxDynamicSharedMemorySize,
                         GEMM_SMEM);
    cudaFuncSetAttribute(gemm_z<2>, cudaFuncAttributeMaxDynamicSharedMemorySize,
                         GEMM_SMEM);

    // fused preprocessing; Wq pre-scaled by QSC
    split_in_kernel<<<(3 * SEG4 + 255) / 256, 256>>>(Fm, Fs, Fq);
    split_w_kernel<<<(WTOT4 + 255) / 256, 256>>>(Wq, Wk, Wv, w1, w2);

    const size_t wO1 = (size_t)1 * DMODEL * DMODEL;
    const size_t wO2 = (size_t)2 * DMODEL * DMODEL;
    const size_t h1  = (size_t)1 * DHID * DMODEL;
    const size_t h2o = (size_t)2 * DHID * DMODEL;

    // ---- batched QKV for blocks 0, 1 + block2's K (z = 6) ----
    {
        GArgs a = {};
        // z0..2: block0 Q/K/V ; z3..5: block1 ; z6: block2 K
        a.ah[0] = fsh; a.al[0] = fsl; a.bh[0] = wqh;      a.bl[0] = wql;      a.ch[0] = qb;
        a.ah[1] = fsh; a.al[1] = fsl; a.bh[1] = wkh;      a.bl[1] = wkl;      a.ch[1] = kb;
        a.ah[2] = fmh; a.al[2] = fml; a.bh[2] = wvh;      a.bl[2] = wvl;      a.ch[2] = vb;
        a.ah[3] = fqh; a.al[3] = fql; a.bh[3] = wqh + wO1; a.bl[3] = wql + wO1; a.ch[3] = qb2;
        a.ah[4] = fqh; a.al[4] = fql; a.bh[4] = wkh + wO1; a.bl[4] = wkl + wO1; a.ch[4] = kb2;
        a.ah[5] = fqh; a.al[5] = fql; a.bh[5] = wvh + wO1; a.bl[5] = wvl + wO1; a.ch[5] = vb2;
        a.ah[6] = fsh; a.al[6] = fsl; a.bh[6] = wkh + wO2; a.bl[6] = wkl + wO2; a.ch[6] = kb3;
        gemm_z<2><<<dim3(DMODEL / TBN, MTOT / TBM, 7), 128, GEMM_SMEM>>>(a, DMODEL, DMODEL);
    }

    // ---- batched flash (blocks 0, 1) ----
    flash_tc<<<dim3(SEQ / FM, NHEADS, 2 * BATCH), 128, FA_SMEM_BYTES>>>(
        qb, kb, vb, att, qb2, kb2, vb2, att2);

    // ---- LN after attention (two launches) ----
    add_ln_kernel<<<MTOT, 128>>>(att,  Fm, lng,          lnb,          1e-5f, x,  xh,  xl,  1);
    add_ln_kernel<<<MTOT, 128>>>(att2, Fq, lng + DMODEL, lnb + DMODEL, 1e-5f, x2, xh2, xl2, 1);

    // ---- batched FFN1 (relu + split) ----
    {
        GArgs a = {};
        a.ah[0] = xh;  a.al[0] = xl;  a.bh[0] = w1h;      a.bl[0] = w1l;      a.ch[0] = hh;  a.cl[0] = hl;
        a.ah[1] = xh2; a.al[1] = xl2; a.bh[1] = w1h + h1; a.bl[1] = w1l + h1; a.ch[1] = hh2; a.cl[1] = hl2;
        gemm_z<1><<<dim3(DHID / TBN, MTOT / TBM, 2), 128, GEMM_SMEM>>>(a, DHID, DMODEL);
    }

    // ---- batched FFN2 (fp32 out) ----
    {
        GArgs a = {};
        a.ah[0] = hh;  a.al[0] = hl;  a.bh[0] = w2h;      a.bl[0] = w2l;      a.c[0] = y;
        a.ah[1] = hh2; a.al[1] = hl2; a.bh[1] = w2h + h1; a.bl[1] = w2l + h1; a.c[1] = y2;
        gemm_z<0><<<dim3(DMODEL / TBN, MTOT / TBM, 2), 128, GEMM_SMEM>>>(a, DMODEL, DHID);
    }

    // ---- final LN of blocks 0, 1 (with splits for block 2) ----
    add_ln_kernel<<<MTOT, 128>>>(y,  x,  flg,          flb,          1e-6f, css, cssh, cssl, 1);
    add_ln_kernel<<<MTOT, 128>>>(y2, x2, flg + DMODEL, flb + DMODEL, 1e-6f, cqq, cqqh, cqql, 1);

    // ================= block 2: csq = blk(2, cqq, Fs, css, css) =============
    {
        GArgs a = {};
        a.ah[0] = cqqh; a.al[0] = cqql; a.bh[0] = wqh + wO2; a.bl[0] = wql + wO2; a.ch[0] = qb;
        a.ah[1] = cssh; a.al[1] = cssl; a.bh[1] = wvh + wO2; a.bl[1] = wvl + wO2; a.ch[1] = vb;
        gemm_z<2><<<dim3(DMODEL / TBN, MTOT / TBM, 2), 128, GEMM_SMEM>>>(a, DMODEL, DMODEL);
    }
    flash_tc<<<dim3(SEQ / FM, NHEADS, BATCH), 128, FA_SMEM_BYTES>>>(
        qb, kb3, vb, att, qb, kb3, vb, att);
    add_ln_kernel<<<MTOT, 128>>>(att, css, lng + 2 * DMODEL, lnb + 2 * DMODEL,
                                 1e-5f, x, xh, xl, 1);
    {
        GArgs a = {};
        a.ah[0] = xh; a.al[0] = xl; a.bh[0] = w1h + h2o; a.bl[0] = w1l + h2o;
        a.ch[0] = hh; a.cl[0] = hl;
        gemm_z<1><<<dim3(DHID / TBN, MTOT / TBM, 1), 128, GEMM_SMEM>>>(a, DHID, DMODEL);
    }
    {
        GArgs a = {};
        a.ah[0] = hh; a.al[0] = hl; a.bh[0] = w2h + h2o; a.bl[0] = w2l + h2o; a.c[0] = y;
        gemm_z<0><<<dim3(DMODEL / TBN, MTOT / TBM, 1), 128, GEMM_SMEM>>>(a, DMODEL, DHID);
    }
    add_ln_kernel<<<MTOT, 128>>>(y, x, flg + 2 * DMODEL, flb + 2 * DMODEL,
                                 1e-6f, out, nullptr, nullptr, 0);
}